// round 4
// baseline (speedup 1.0000x reference)
#include <cuda_runtime.h>
#include <cstdint>

#define NB 4
#define NV 20000
#define NP 400000
#define NNETS 50000
#define MPINS 32
#define GRID 64

// -------- static scratch (no allocation allowed) --------
__device__ float  d_pin_pos[NP * 8];          // [P][B][2] interleaved -> 2x float4 per pin
__device__ float  d_bbox[NNETS * NB * 4];     // per (net,batch): xmin,xmax,ymin,ymax (grid units)
__device__ float  d_rudy[NB * GRID * GRID];
__device__ double d_hpwl[NB];

// ---------------- init ----------------
__global__ void k_init() {
    int t = blockIdx.x * blockDim.x + threadIdx.x;
    int n = NB * GRID * GRID;
    for (int i = t; i < n; i += gridDim.x * blockDim.x) d_rudy[i] = 0.f;
    if (t < NB) d_hpwl[t] = 0.0;
}

// ---------------- pin positions ----------------
__global__ __launch_bounds__(256) void k_pinpos(
    const float* __restrict__ pos,   // (B,V,2)
    const float* __restrict__ roh,   // (B,V,4)
    const int*   __restrict__ p2m,   // (P,)
    const float* __restrict__ poff)  // (P,2)
{
    int p = blockIdx.x * blockDim.x + threadIdx.x;
    if (p >= NP) return;
    int m = p2m[p];
    float2 off = ((const float2*)poff)[p];
    float o[8];
#pragma unroll
    for (int b = 0; b < NB; b++) {
        float2 mp = ((const float2*)pos)[b * NV + m];
        float4 oh = ((const float4*)roh)[b * NV + m];
        float c = oh.x - oh.z;  // rotations 0..3 collapse to cos/sin in {-1,0,1}
        float s = oh.y - oh.w;
        o[2 * b + 0] = mp.x + c * off.x - s * off.y;
        o[2 * b + 1] = mp.y + s * off.x + c * off.y;
    }
    float4* dst = (float4*)d_pin_pos + p * 2;
    dst[0] = make_float4(o[0], o[1], o[2], o[3]);
    dst[1] = make_float4(o[4], o[5], o[6], o[7]);
}

// ---------------- per-net LSE wirelength + bbox (warp per net) ----------------
__device__ __forceinline__ float wredmax(float v) {
#pragma unroll
    for (int o = 16; o > 0; o >>= 1) v = fmaxf(v, __shfl_xor_sync(0xffffffffu, v, o));
    return v;
}
__device__ __forceinline__ float wredmin(float v) {
#pragma unroll
    for (int o = 16; o > 0; o >>= 1) v = fminf(v, __shfl_xor_sync(0xffffffffu, v, o));
    return v;
}
__device__ __forceinline__ float wredsum(float v) {
#pragma unroll
    for (int o = 16; o > 0; o >>= 1) v += __shfl_xor_sync(0xffffffffu, v, o);
    return v;
}

__global__ __launch_bounds__(256) void k_net(
    const int*   __restrict__ n2p,   // (NN,32)
    const float* __restrict__ nw)    // (NN,)
{
    int n    = (blockIdx.x * blockDim.x + threadIdx.x) >> 5;
    int lane = threadIdx.x & 31;
    int wIn  = threadIdx.x >> 5;
    __shared__ float s_wl[8][NB];

    bool act = (n < NNETS);
    bool valid = false;
    float v[NB][2];
#pragma unroll
    for (int b = 0; b < NB; b++) { v[b][0] = 0.f; v[b][1] = 0.f; }

    if (act) {
        int idx = __ldg(&n2p[n * MPINS + lane]);
        valid = idx >= 0;
        int q = valid ? idx : 0;
        const float4* pp = (const float4*)d_pin_pos + q * 2;
        float4 lo = pp[0], hi = pp[1];
        v[0][0] = lo.x; v[0][1] = lo.y;
        v[1][0] = lo.z; v[1][1] = lo.w;
        v[2][0] = hi.x; v[2][1] = hi.y;
        v[3][0] = hi.z; v[3][1] = hi.w;
    }

    float mx[NB][2], mn[NB][2], smax[NB][2], smin[NB][2];
#pragma unroll
    for (int b = 0; b < NB; b++)
#pragma unroll
        for (int a = 0; a < 2; a++) {
            float val = v[b][a];
            float tmax = valid ? val : -1e9f;
            float tmin = valid ? val :  1e9f;
            mx[b][a] = wredmax(tmax);
            mn[b][a] = wredmin(tmin);
            float e1 = valid ? __expf(10.f * (val - mx[b][a])) : 0.f;
            float e2 = valid ? __expf(10.f * (mn[b][a] - val)) : 0.f;
            smax[b][a] = wredsum(e1);
            smin[b][a] = wredsum(e2);
        }

    if (lane == 0) {
        if (act) {
            float w = __ldg(&nw[n]);
#pragma unroll
            for (int b = 0; b < NB; b++) {
                float lmaxx = mx[b][0] + __logf(smax[b][0]) * 0.1f;
                float lminx = mn[b][0] - __logf(smin[b][0]) * 0.1f;
                float lmaxy = mx[b][1] + __logf(smax[b][1]) * 0.1f;
                float lminy = mn[b][1] - __logf(smin[b][1]) * 0.1f;
                s_wl[wIn][b] = w * ((lmaxx - lminx) + (lmaxy - lminy));
                float4 bb;
                bb.x = (mn[b][0] + 1.f) * 31.5f;   // (M-1)/2
                bb.y = (mx[b][0] + 1.f) * 31.5f;
                bb.z = (mn[b][1] + 1.f) * 31.5f;
                bb.w = (mx[b][1] + 1.f) * 31.5f;
                ((float4*)d_bbox)[n * NB + b] = bb;
            }
        } else {
#pragma unroll
            for (int b = 0; b < NB; b++) s_wl[wIn][b] = 0.f;
        }
    }
    __syncthreads();
    if (threadIdx.x < NB) {
        double acc = 0.0;
#pragma unroll
        for (int wq = 0; wq < 8; wq++) acc += (double)s_wl[wq][threadIdx.x];
        atomicAdd(&d_hpwl[threadIdx.x], acc);
    }
}

// ---------------- congestion: split-K rank-1 accumulation GEMM ----------------
#define NKC 32

__global__ __launch_bounds__(256) void k_cong() {
    __shared__ float s_x[NKC][GRID];
    __shared__ float s_y[NKC][GRID];
    int tid  = threadIdx.x;
    int nPer = (NNETS + (int)gridDim.x - 1) / (int)gridDim.x;
    int n0   = blockIdx.x * nPer;
    int n1   = min(n0 + nPer, NNETS);
    int j0   = (tid & 15) * 4;
    int i0   = (tid >> 4) * 4;

    for (int b = 0; b < NB; b++) {
        unsigned long long acc[4][2];   // f32x2 packed accumulators
#pragma unroll
        for (int ii = 0; ii < 4; ii++) { acc[ii][0] = 0ull; acc[ii][1] = 0ull; }

        for (int c = n0; c < n1; c += NKC) {
            int nk = min(NKC, n1 - c);
            __syncthreads();
            // fill in_x / (in_y / bbox_size): geometric sigmoid-product recurrence
            for (int it = tid; it < nk * 16; it += 256) {
                int k   = it >> 4;
                int sub = it & 15;
                int a   = sub >> 3;          // 0 = x axis, 1 = y axis
                int g0  = (sub & 7) * 8;     // 8 cells per item
                float4 bb = ((const float4*)d_bbox)[(c + k) * NB + b];
                float lmn = a ? bb.z : bb.x;
                float lmx = a ? bb.w : bb.y;
                float u   = __expf(2.f * (lmn - (float)g0) - 1.f);
                float vv  = __expf(2.f * ((float)g0 - lmx) - 1.f);
                float Cc  = __expf(-2.f * (lmx - lmn + 1.f));
                float base = 1.f + Cc;
                float scale = 1.f;
                if (a) {
                    float bs = fmaxf((bb.y - bb.x + 1.f) * (bb.w - bb.z + 1.f), 1.f);
                    scale = __fdividef(1.f, bs);
                }
                float* dst = a ? &s_y[k][g0] : &s_x[k][g0];
#pragma unroll
                for (int g = 0; g < 8; g++) {
                    float denom = base + u + vv;        // = (1+e^-a)(1+e^-b)
                    dst[g] = __fdividef(scale, denom);  // sigmoid product (*1/bs for y)
                    u  *= 0.13533528323661270f;         // e^-2
                    vv *= 7.3890560989306495f;          // e^+2
                }
            }
            __syncthreads();
            for (int k = 0; k < nk; k++) {
                float4 xv = *(const float4*)&s_x[k][j0];
                float4 yv = *(const float4*)&s_y[k][i0];
                unsigned long long x01, x23;
                asm("mov.b64 %0, {%1, %2};" : "=l"(x01) : "f"(xv.x), "f"(xv.y));
                asm("mov.b64 %0, {%1, %2};" : "=l"(x23) : "f"(xv.z), "f"(xv.w));
                float ys0 = yv.x, ys1 = yv.y, ys2 = yv.z, ys3 = yv.w;
                unsigned long long yy;
                asm("mov.b64 %0, {%1, %1};" : "=l"(yy) : "f"(ys0));
                asm("fma.rn.f32x2 %0, %1, %2, %0;" : "+l"(acc[0][0]) : "l"(yy), "l"(x01));
                asm("fma.rn.f32x2 %0, %1, %2, %0;" : "+l"(acc[0][1]) : "l"(yy), "l"(x23));
                asm("mov.b64 %0, {%1, %1};" : "=l"(yy) : "f"(ys1));
                asm("fma.rn.f32x2 %0, %1, %2, %0;" : "+l"(acc[1][0]) : "l"(yy), "l"(x01));
                asm("fma.rn.f32x2 %0, %1, %2, %0;" : "+l"(acc[1][1]) : "l"(yy), "l"(x23));
                asm("mov.b64 %0, {%1, %1};" : "=l"(yy) : "f"(ys2));
                asm("fma.rn.f32x2 %0, %1, %2, %0;" : "+l"(acc[2][0]) : "l"(yy), "l"(x01));
                asm("fma.rn.f32x2 %0, %1, %2, %0;" : "+l"(acc[2][1]) : "l"(yy), "l"(x23));
                asm("mov.b64 %0, {%1, %1};" : "=l"(yy) : "f"(ys3));
                asm("fma.rn.f32x2 %0, %1, %2, %0;" : "+l"(acc[3][0]) : "l"(yy), "l"(x01));
                asm("fma.rn.f32x2 %0, %1, %2, %0;" : "+l"(acc[3][1]) : "l"(yy), "l"(x23));
            }
        }
#pragma unroll
        for (int ii = 0; ii < 4; ii++) {
            float a0, a1, a2, a3;
            asm("mov.b64 {%0, %1}, %2;" : "=f"(a0), "=f"(a1) : "l"(acc[ii][0]));
            asm("mov.b64 {%0, %1}, %2;" : "=f"(a2), "=f"(a3) : "l"(acc[ii][1]));
            float* r = &d_rudy[b * GRID * GRID + (i0 + ii) * GRID + j0];
            atomicAdd(r + 0, a0);
            atomicAdd(r + 1, a1);
            atomicAdd(r + 2, a2);
            atomicAdd(r + 3, a3);
        }
    }
}

// ---------------- separable Gaussian smooth + overflow penalty + final ----------------
__global__ __launch_bounds__(256) void k_final(float* __restrict__ out) {
    int b = blockIdx.x;
    __shared__ float s_in[GRID][GRID];
    __shared__ float s_tmp[GRID][GRID];
    __shared__ float s_red[256];
    int tid = threadIdx.x;

    float w[7];
    {
        float sum = 0.f;
#pragma unroll
        for (int i = 0; i < 7; i++) {
            float x = (float)(i - 3);
            w[i] = expf(-x * x / 4.5f);   // 2*sigma^2 = 4.5
            sum += w[i];
        }
        float inv = 1.f / sum;
#pragma unroll
        for (int i = 0; i < 7; i++) w[i] *= inv;  // outer(w,w) == normalized 2D kernel
    }

    for (int i = tid; i < GRID * GRID; i += 256)
        s_in[i >> 6][i & 63] = d_rudy[b * GRID * GRID + i];
    __syncthreads();

    for (int i = tid; i < GRID * GRID; i += 256) {
        int r = i >> 6, cx = i & 63;
        float acc = 0.f;
#pragma unroll
        for (int d = -3; d <= 3; d++) {
            int rr = r + d;
            if (rr >= 0 && rr < GRID) acc = fmaf(w[d + 3], s_in[rr][cx], acc);
        }
        s_tmp[r][cx] = acc;
    }
    __syncthreads();

    float pen = 0.f;
    for (int i = tid; i < GRID * GRID; i += 256) {
        int r = i >> 6, cx = i & 63;
        float acc = 0.f;
#pragma unroll
        for (int d = -3; d <= 3; d++) {
            int cc = cx + d;
            if (cc >= 0 && cc < GRID) acc = fmaf(w[d + 3], s_tmp[r][cc], acc);
        }
        float o = acc - 1.f;            // THRESH = 1
        if (o > 0.f) pen = fmaf(o, o, pen);
    }
    s_red[tid] = pen;
    __syncthreads();
    for (int s = 128; s > 0; s >>= 1) {
        if (tid < s) s_red[tid] += s_red[tid + s];
        __syncthreads();
    }
    if (tid == 0)
        out[b] = (float)(d_hpwl[b] + 0.5 * (double)s_red[0]);  // W_WL=1, W_CONG=0.5
}

// ---------------- launcher ----------------
extern "C" void kernel_launch(void* const* d_in, const int* in_sizes, int n_in,
                              void* d_out, int out_size)
{
    const float* positions = nullptr;
    const int*   n2p = nullptr;
    const int*   p2m = nullptr;
    const float* poff = nullptr;
    const float* roh = nullptr;
    const float* nw = nullptr;

    for (int i = 0; i < n_in; i++) {
        switch (in_sizes[i]) {                      // all element counts distinct
            case NB * NV * 2:    positions = (const float*)d_in[i]; break; // 160000
            case NNETS * MPINS:  n2p       = (const int*)  d_in[i]; break; // 1600000
            case NP:             p2m       = (const int*)  d_in[i]; break; // 400000
            case NP * 2:         poff      = (const float*)d_in[i]; break; // 800000
            case NB * NV * 4:    roh       = (const float*)d_in[i]; break; // 320000
            case NNETS:          nw        = (const float*)d_in[i]; break; // 50000
            default: break;
        }
    }
    if (!positions || !n2p || !p2m || !poff || !roh || !nw) return;

    k_init<<<16, 256>>>();
    k_pinpos<<<(NP + 255) / 256, 256>>>(positions, roh, p2m, poff);
    k_net<<<(NNETS + 7) / 8, 256>>>(n2p, nw);
    k_cong<<<148, 256>>>();
    k_final<<<NB, 256>>>((float*)d_out);
}

// round 5
// speedup vs baseline: 1.4201x; 1.4201x over previous
#include <cuda_runtime.h>
#include <cstdint>

#define NB 4
#define NV 20000
#define NP 400000
#define NNETS 50000
#define MPINS 32
#define GRID 64

// -------- static scratch (no allocation allowed) --------
__device__ float  d_pin_pos[NP * 8];          // [P][B][2] interleaved -> 2x float4 per pin
__device__ float  d_bbox[NNETS * NB * 4];     // per (net,batch): xmin,xmax,ymin,ymax (grid units)
__device__ float  d_rudy[NB * GRID * GRID];
__device__ double d_hpwl[NB];

// ---------------- init ----------------
__global__ void k_init() {
    int t = blockIdx.x * blockDim.x + threadIdx.x;
    int n = NB * GRID * GRID;
    for (int i = t; i < n; i += gridDim.x * blockDim.x) d_rudy[i] = 0.f;
    if (t < NB) d_hpwl[t] = 0.0;
}

// ---------------- pin positions ----------------
__global__ __launch_bounds__(256) void k_pinpos(
    const float* __restrict__ pos,   // (B,V,2)
    const float* __restrict__ roh,   // (B,V,4)
    const int*   __restrict__ p2m,   // (P,)
    const float* __restrict__ poff)  // (P,2)
{
    int p = blockIdx.x * blockDim.x + threadIdx.x;
    if (p >= NP) return;
    int m = p2m[p];
    float2 off = ((const float2*)poff)[p];
    float o[8];
#pragma unroll
    for (int b = 0; b < NB; b++) {
        float2 mp = ((const float2*)pos)[b * NV + m];
        float4 oh = ((const float4*)roh)[b * NV + m];
        float c = oh.x - oh.z;  // rotations 0..3 collapse to cos/sin in {-1,0,1}
        float s = oh.y - oh.w;
        o[2 * b + 0] = mp.x + c * off.x - s * off.y;
        o[2 * b + 1] = mp.y + s * off.x + c * off.y;
    }
    float4* dst = (float4*)d_pin_pos + p * 2;
    dst[0] = make_float4(o[0], o[1], o[2], o[3]);
    dst[1] = make_float4(o[4], o[5], o[6], o[7]);
}

// ---------------- per-net LSE wirelength + bbox ----------------
// 4 nets per warp: 8 lanes per net, 4 pin slots per lane.
// All 4 nets' reductions share the same 3-step (xor 4,2,1) butterfly.
__global__ __launch_bounds__(256) void k_net(
    const int*   __restrict__ n2p,   // (NN,32)
    const float* __restrict__ nw)    // (NN,)
{
    int warpG = (blockIdx.x * blockDim.x + threadIdx.x) >> 5;
    int lane  = threadIdx.x & 31;
    int grp   = lane >> 3;           // net slot within warp (0..3)
    int r     = lane & 7;            // lane within group
    int net   = warpG * 4 + grp;
    bool act  = (net < NNETS);

    float mx[NB][2], mn[NB][2], s1[NB][2], s2[NB][2];
#pragma unroll
    for (int b = 0; b < NB; b++)
#pragma unroll
        for (int a = 0; a < 2; a++) {
            mx[b][a] = -1e9f; mn[b][a] = 1e9f;
            s1[b][a] = 0.f;   s2[b][a] = 0.f;
        }

    if (act) {
        int4 idx4 = __ldg((const int4*)n2p + net * 8 + r);
        int idxs[4] = {idx4.x, idx4.y, idx4.z, idx4.w};
#pragma unroll
        for (int s = 0; s < 4; s++) {
            int idx = idxs[s];
            if (idx >= 0) {
                const float4* pp = (const float4*)d_pin_pos + (size_t)idx * 2;
                float4 lo = __ldg(pp), hi = __ldg(pp + 1);
                float v[NB][2] = {{lo.x, lo.y}, {lo.z, lo.w}, {hi.x, hi.y}, {hi.z, hi.w}};
#pragma unroll
                for (int b = 0; b < NB; b++)
#pragma unroll
                    for (int a = 0; a < 2; a++) {
                        float val = v[b][a];
                        mx[b][a] = fmaxf(mx[b][a], val);
                        mn[b][a] = fminf(mn[b][a], val);
                        // exact wrt reference: exp(10(v-max)) summed = e^{-10max} * sum e^{10v};
                        // bounded (|v|<=1 -> e^10), masked slots contribute exactly 0.
                        s1[b][a] += __expf( 10.f * val);
                        s2[b][a] += __expf(-10.f * val);
                    }
            }
        }
    }

    // 3-step butterfly within each 8-lane group (xor offsets 4,2,1 stay in-group)
#pragma unroll
    for (int o = 4; o > 0; o >>= 1) {
#pragma unroll
        for (int b = 0; b < NB; b++)
#pragma unroll
            for (int a = 0; a < 2; a++) {
                mx[b][a] = fmaxf(mx[b][a], __shfl_xor_sync(0xffffffffu, mx[b][a], o));
                mn[b][a] = fminf(mn[b][a], __shfl_xor_sync(0xffffffffu, mn[b][a], o));
                s1[b][a] += __shfl_xor_sync(0xffffffffu, s1[b][a], o);
                s2[b][a] += __shfl_xor_sync(0xffffffffu, s2[b][a], o);
            }
    }

    float wl[NB] = {0.f, 0.f, 0.f, 0.f};
    if (r == 0 && act) {
        float w = __ldg(&nw[net]);
#pragma unroll
        for (int b = 0; b < NB; b++) {
            // (lse_max - lse_min) over both axes == 0.1 * log(S1x*S2x*S1y*S2y)
            float prod = (s1[b][0] * s2[b][0]) * (s1[b][1] * s2[b][1]);
            wl[b] = w * 0.1f * __logf(prod);
            float4 bb;
            bb.x = (mn[b][0] + 1.f) * 31.5f;   // (M-1)/2
            bb.y = (mx[b][0] + 1.f) * 31.5f;
            bb.z = (mn[b][1] + 1.f) * 31.5f;
            bb.w = (mx[b][1] + 1.f) * 31.5f;
            ((float4*)d_bbox)[net * NB + b] = bb;
        }
    }
    // sum the 4 group leaders (lanes 0,8,16,24; others hold 0) -> lane 0
#pragma unroll
    for (int b = 0; b < NB; b++) {
        wl[b] += __shfl_xor_sync(0xffffffffu, wl[b], 8);
        wl[b] += __shfl_xor_sync(0xffffffffu, wl[b], 16);
    }

    __shared__ double s_h[NB];
    if (threadIdx.x < NB) s_h[threadIdx.x] = 0.0;
    __syncthreads();
    if (lane == 0) {
#pragma unroll
        for (int b = 0; b < NB; b++) atomicAdd(&s_h[b], (double)wl[b]);
    }
    __syncthreads();
    if (threadIdx.x < NB) atomicAdd(&d_hpwl[threadIdx.x], s_h[threadIdx.x]);
}

// ---------------- congestion: split-K rank-1 accumulation GEMM ----------------
// One block per (batch, K-chunk group): grid = 148 groups * 4 batches = 592
// -> 4 CTAs per SM resident (was 1), hides FFMA/LDS latency.
#define NKC 32
#define NGROUPS 148

__global__ __launch_bounds__(256) void k_cong() {
    __shared__ float s_x[NKC][GRID];
    __shared__ float s_y[NKC][GRID];
    int tid   = threadIdx.x;
    int b     = blockIdx.x & 3;
    int group = blockIdx.x >> 2;
    const int nPer = (NNETS + NGROUPS - 1) / NGROUPS;
    int n0 = group * nPer;
    int n1 = min(n0 + nPer, NNETS);
    int j0 = (tid & 15) * 4;
    int i0 = (tid >> 4) * 4;

    unsigned long long acc[4][2];   // f32x2 packed accumulators
#pragma unroll
    for (int ii = 0; ii < 4; ii++) { acc[ii][0] = 0ull; acc[ii][1] = 0ull; }

    for (int c = n0; c < n1; c += NKC) {
        int nk = min(NKC, n1 - c);
        __syncthreads();
        // fill in_x / (in_y / bbox_size): geometric sigmoid-product recurrence
        for (int it = tid; it < nk * 16; it += 256) {
            int k   = it >> 4;
            int sub = it & 15;
            int a   = sub >> 3;          // 0 = x axis, 1 = y axis
            int g0  = (sub & 7) * 8;     // 8 cells per item
            float4 bb = __ldg((const float4*)d_bbox + (c + k) * NB + b);
            float lmn = a ? bb.z : bb.x;
            float lmx = a ? bb.w : bb.y;
            float u   = __expf(2.f * (lmn - (float)g0) - 1.f);
            float vv  = __expf(2.f * ((float)g0 - lmx) - 1.f);
            float Cc  = __expf(-2.f * (lmx - lmn + 1.f));
            float base = 1.f + Cc;
            float scale = 1.f;
            if (a) {
                float bs = fmaxf((bb.y - bb.x + 1.f) * (bb.w - bb.z + 1.f), 1.f);
                scale = __fdividef(1.f, bs);
            }
            float* dst = a ? &s_y[k][g0] : &s_x[k][g0];
#pragma unroll
            for (int g = 0; g < 8; g++) {
                float denom = base + u + vv;        // = (1+e^-a)(1+e^-b)
                dst[g] = __fdividef(scale, denom);  // sigmoid product (*1/bs for y)
                u  *= 0.13533528323661270f;         // e^-2
                vv *= 7.3890560989306495f;          // e^+2
            }
        }
        __syncthreads();
        for (int k = 0; k < nk; k++) {
            float4 xv = *(const float4*)&s_x[k][j0];
            float4 yv = *(const float4*)&s_y[k][i0];
            unsigned long long x01, x23;
            asm("mov.b64 %0, {%1, %2};" : "=l"(x01) : "f"(xv.x), "f"(xv.y));
            asm("mov.b64 %0, {%1, %2};" : "=l"(x23) : "f"(xv.z), "f"(xv.w));
            unsigned long long yy;
            asm("mov.b64 %0, {%1, %1};" : "=l"(yy) : "f"(yv.x));
            asm("fma.rn.f32x2 %0, %1, %2, %0;" : "+l"(acc[0][0]) : "l"(yy), "l"(x01));
            asm("fma.rn.f32x2 %0, %1, %2, %0;" : "+l"(acc[0][1]) : "l"(yy), "l"(x23));
            asm("mov.b64 %0, {%1, %1};" : "=l"(yy) : "f"(yv.y));
            asm("fma.rn.f32x2 %0, %1, %2, %0;" : "+l"(acc[1][0]) : "l"(yy), "l"(x01));
            asm("fma.rn.f32x2 %0, %1, %2, %0;" : "+l"(acc[1][1]) : "l"(yy), "l"(x23));
            asm("mov.b64 %0, {%1, %1};" : "=l"(yy) : "f"(yv.z));
            asm("fma.rn.f32x2 %0, %1, %2, %0;" : "+l"(acc[2][0]) : "l"(yy), "l"(x01));
            asm("fma.rn.f32x2 %0, %1, %2, %0;" : "+l"(acc[2][1]) : "l"(yy), "l"(x23));
            asm("mov.b64 %0, {%1, %1};" : "=l"(yy) : "f"(yv.w));
            asm("fma.rn.f32x2 %0, %1, %2, %0;" : "+l"(acc[3][0]) : "l"(yy), "l"(x01));
            asm("fma.rn.f32x2 %0, %1, %2, %0;" : "+l"(acc[3][1]) : "l"(yy), "l"(x23));
        }
    }
#pragma unroll
    for (int ii = 0; ii < 4; ii++) {
        float a0, a1, a2, a3;
        asm("mov.b64 {%0, %1}, %2;" : "=f"(a0), "=f"(a1) : "l"(acc[ii][0]));
        asm("mov.b64 {%0, %1}, %2;" : "=f"(a2), "=f"(a3) : "l"(acc[ii][1]));
        float* rr = &d_rudy[b * GRID * GRID + (i0 + ii) * GRID + j0];
        atomicAdd(rr + 0, a0);
        atomicAdd(rr + 1, a1);
        atomicAdd(rr + 2, a2);
        atomicAdd(rr + 3, a3);
    }
}

// ---------------- separable Gaussian smooth + overflow penalty + final ----------------
__global__ __launch_bounds__(256) void k_final(float* __restrict__ out) {
    int b = blockIdx.x;
    __shared__ float s_in[GRID][GRID];
    __shared__ float s_tmp[GRID][GRID];
    __shared__ float s_red[256];
    int tid = threadIdx.x;

    float w[7];
    {
        float sum = 0.f;
#pragma unroll
        for (int i = 0; i < 7; i++) {
            float x = (float)(i - 3);
            w[i] = expf(-x * x / 4.5f);   // 2*sigma^2 = 4.5
            sum += w[i];
        }
        float inv = 1.f / sum;
#pragma unroll
        for (int i = 0; i < 7; i++) w[i] *= inv;  // outer(w,w) == normalized 2D kernel
    }

    for (int i = tid; i < GRID * GRID; i += 256)
        s_in[i >> 6][i & 63] = d_rudy[b * GRID * GRID + i];
    __syncthreads();

    for (int i = tid; i < GRID * GRID; i += 256) {
        int r = i >> 6, cx = i & 63;
        float acc = 0.f;
#pragma unroll
        for (int d = -3; d <= 3; d++) {
            int rr = r + d;
            if (rr >= 0 && rr < GRID) acc = fmaf(w[d + 3], s_in[rr][cx], acc);
        }
        s_tmp[r][cx] = acc;
    }
    __syncthreads();

    float pen = 0.f;
    for (int i = tid; i < GRID * GRID; i += 256) {
        int r = i >> 6, cx = i & 63;
        float acc = 0.f;
#pragma unroll
        for (int d = -3; d <= 3; d++) {
            int cc = cx + d;
            if (cc >= 0 && cc < GRID) acc = fmaf(w[d + 3], s_tmp[r][cc], acc);
        }
        float o = acc - 1.f;            // THRESH = 1
        if (o > 0.f) pen = fmaf(o, o, pen);
    }
    s_red[tid] = pen;
    __syncthreads();
    for (int s = 128; s > 0; s >>= 1) {
        if (tid < s) s_red[tid] += s_red[tid + s];
        __syncthreads();
    }
    if (tid == 0)
        out[b] = (float)(d_hpwl[b] + 0.5 * (double)s_red[0]);  // W_WL=1, W_CONG=0.5
}

// ---------------- launcher ----------------
extern "C" void kernel_launch(void* const* d_in, const int* in_sizes, int n_in,
                              void* d_out, int out_size)
{
    const float* positions = nullptr;
    const int*   n2p = nullptr;
    const int*   p2m = nullptr;
    const float* poff = nullptr;
    const float* roh = nullptr;
    const float* nw = nullptr;

    for (int i = 0; i < n_in; i++) {
        switch (in_sizes[i]) {                      // all element counts distinct
            case NB * NV * 2:    positions = (const float*)d_in[i]; break; // 160000
            case NNETS * MPINS:  n2p       = (const int*)  d_in[i]; break; // 1600000
            case NP:             p2m       = (const int*)  d_in[i]; break; // 400000
            case NP * 2:         poff      = (const float*)d_in[i]; break; // 800000
            case NB * NV * 4:    roh       = (const float*)d_in[i]; break; // 320000
            case NNETS:          nw        = (const float*)d_in[i]; break; // 50000
            default: break;
        }
    }
    if (!positions || !n2p || !p2m || !poff || !roh || !nw) return;

    k_init<<<16, 256>>>();
    k_pinpos<<<(NP + 255) / 256, 256>>>(positions, roh, p2m, poff);
    k_net<<<(NNETS + 31) / 32, 256>>>(n2p, nw);
    k_cong<<<4 * NGROUPS, 256>>>();
    k_final<<<NB, 256>>>((float*)d_out);
}